// round 15
// baseline (speedup 1.0000x reference)
#include <cuda_runtime.h>
#include <cuda_fp16.h>
#include <cstdint>

#define N_NODES 50000
#define N_EDGES 800000
#define EN      (N_EDGES + N_NODES)
#define NB      ((N_NODES + 255) / 256)
#define NE2     (N_EDGES / 2)
#define NE4     (N_EDGES / 4)

// ---------------- scratch (device globals; no allocation) ----------------
__device__ __half g_xh[(size_t)N_NODES * 256];   // x fp16
__device__ __half g_w1h[256 * 256];              // W1 fp16
__device__ __half g_w2h[128 * 256];              // W2 fp16
__device__ __half g_o1h[(size_t)N_NODES * 256];  // layer1 GAT out fp16
__device__ __half g_h1h[(size_t)N_NODES * 256];  // layer1 linear out fp16
__device__ __half g_h2h[(size_t)N_NODES * 128];  // layer2 linear out fp16
__device__ float  g_as1[N_NODES * 2];
__device__ float  g_ad1[N_NODES * 2];
__device__ float  g_as2[N_NODES];
__device__ float  g_ad2[N_NODES];
__device__ int    g_deg[N_NODES + 8];
__device__ int    g_off[N_NODES + 8];
__device__ int    g_rank[N_EDGES];
__device__ int    g_csr_src[EN];
__device__ int    g_is64;
__device__ unsigned long long g_state[NB + 8];   // decoupled-lookback scan state

// ---------------- helpers ----------------
__device__ __forceinline__ uint32_t swz(uint32_t b) { return b ^ ((b >> 3) & 0x70); }

__device__ __forceinline__ uint32_t pack_h2(__half a, __half b) {
    __half2 t(a, b);
    return *reinterpret_cast<uint32_t*>(&t);
}

__device__ __forceinline__ void cp16(uint32_t dst, const void* src, int sz) {
    asm volatile("cp.async.cg.shared.global [%0], [%1], 16, %2;\n"
                 :: "r"(dst), "l"(src), "r"(sz) : "memory");
}
__device__ __forceinline__ void cp_commit() {
    asm volatile("cp.async.commit_group;\n" ::: "memory");
}
__device__ __forceinline__ void cp_wait1() {
    asm volatile("cp.async.wait_group 1;\n" ::: "memory");
}

__device__ __forceinline__ void mma_fp16(float& c0, float& c1, float& c2, float& c3,
                                         uint32_t a0, uint32_t a1, uint32_t a2, uint32_t a3,
                                         uint32_t b0, uint32_t b1) {
    asm volatile(
        "mma.sync.aligned.m16n8k16.row.col.f32.f16.f16.f32 "
        "{%0,%1,%2,%3}, {%4,%5,%6,%7}, {%8,%9}, {%0,%1,%2,%3};\n"
        : "+f"(c0), "+f"(c1), "+f"(c2), "+f"(c3)
        : "r"(a0), "r"(a1), "r"(a2), "r"(a3), "r"(b0), "r"(b1));
}

__device__ __forceinline__ uint2 cvt4h(float4 v) {
    return make_uint2(pack_h2(__float2half_rn(v.x), __float2half_rn(v.y)),
                      pack_h2(__float2half_rn(v.z), __float2half_rn(v.w)));
}

// ------- prep: x/W fp16 convert + deg init + scan-state zero + dtype detect -------
__global__ void prep_kernel(const float* __restrict__ x,
                            const float* __restrict__ W1src,
                            const float* __restrict__ W2src,
                            const int* __restrict__ ei_w) {
    int i = blockIdx.x * blockDim.x + threadIdx.x;
    const int n4 = N_NODES * 256 / 4;
    const int n1 = 256 * 256 / 4;
    const int n2 = 128 * 256 / 4;
    if (blockIdx.x == 0) {
        if (threadIdx.x == 0) g_is64 = 1;
        __syncthreads();
        if (ei_w[2 * threadIdx.x + 1] != 0) atomicAnd(&g_is64, 0);
    }
    if (i < N_NODES) g_deg[i] = 1;      // self loop
    if (i < NB + 8) g_state[i] = 0ULL;  // scan state reset
    if (i < n1) ((uint2*)g_w1h)[i] = cvt4h(((const float4*)W1src)[i]);
    else if (i < n1 + n2) {
        int idx = i - n1;
        ((uint2*)g_w2h)[idx] = cvt4h(((const float4*)W2src)[idx]);
    }
    if (i < n4) ((uint2*)g_xh)[i] = cvt4h(((const float4*)x)[i]);
}

// ---------------- CSR build ----------------
// histogram + per-edge rank: rank = old count (self loop holds rank 0)
__global__ void hist_kernel(const void* __restrict__ ei) {
    int idx = blockIdx.x * blockDim.x + threadIdx.x;
    if (idx >= NE4) return;
    int d0, d1, d2, d3;
    if (g_is64) {
        const longlong2* p = (const longlong2*)((const long long*)ei + N_EDGES);
        longlong2 a = p[2 * idx], b = p[2 * idx + 1];
        d0 = (int)a.x; d1 = (int)a.y; d2 = (int)b.x; d3 = (int)b.y;
    } else {
        const int4* p = (const int4*)((const int*)ei + N_EDGES);
        int4 d = p[idx];
        d0 = d.x; d1 = d.y; d2 = d.z; d3 = d.w;
    }
    int4 r;
    r.x = atomicAdd(&g_deg[d0], 1);
    r.y = atomicAdd(&g_deg[d1], 1);
    r.z = atomicAdd(&g_deg[d2], 1);
    r.w = atomicAdd(&g_deg[d3], 1);
    ((int4*)g_rank)[idx] = r;
}

// single-pass exclusive scan with decoupled lookback
__global__ void scan_kernel() {
    __shared__ int wsum[8];
    __shared__ int s_prefix;
    int b = blockIdx.x, t = threadIdx.x, lane = t & 31, wid = t >> 5;
    int i = b * 256 + t;
    int v = (i < N_NODES) ? g_deg[i] : 0;
    int x = v;
    #pragma unroll
    for (int o = 1; o < 32; o <<= 1) {
        int y = __shfl_up_sync(0xffffffffu, x, o);
        if (lane >= o) x += y;
    }
    if (lane == 31) wsum[wid] = x;
    __syncthreads();
    if (wid == 0 && lane < 8) {
        int ws = wsum[lane];
        #pragma unroll
        for (int o = 1; o < 8; o <<= 1) {
            int y = __shfl_up_sync(0xffu, ws, o);
            if (lane >= o) ws += y;
        }
        wsum[lane] = ws;
    }
    __syncthreads();
    int incl = x + (wid ? wsum[wid - 1] : 0);
    int btotal = wsum[7];

    if (t == 0) {
        if (b == 0) {
            atomicExch(&g_state[0], (2ULL << 32) | (unsigned)btotal);
            s_prefix = 0;
        } else {
            atomicExch(&g_state[b], (1ULL << 32) | (unsigned)btotal);
            int excl = 0;
            int p = b - 1;
            while (true) {
                unsigned long long s = atomicAdd(&g_state[p], 0ULL);
                unsigned fl = (unsigned)(s >> 32);
                if (fl == 2u) { excl += (int)(unsigned)s; break; }
                if (fl == 1u) { excl += (int)(unsigned)s; p--; }
            }
            atomicExch(&g_state[b], (2ULL << 32) | (unsigned)(excl + btotal));
            s_prefix = excl;
        }
    }
    __syncthreads();
    int e = s_prefix + incl - v;
    if (i < N_NODES) g_off[i] = e;
    if (i == 0) g_off[N_NODES] = EN;
}

// atomic-free scatter: pos = off[dst] + rank[e]; self loops at rank 0
#define SCAT_T (NE2 + N_NODES)
__global__ void scatter_kernel(const void* __restrict__ ei) {
    int idx = blockIdx.x * blockDim.x + threadIdx.x;
    if (idx >= SCAT_T) return;
    if (idx < NE2) {
        int s0, d0, s1, d1;
        if (g_is64) {
            const long long* p = (const long long*)ei;
            const longlong2* ps = (const longlong2*)p;
            const longlong2* pd = (const longlong2*)(p + N_EDGES);
            longlong2 sv = ps[idx], dv = pd[idx];
            s0 = (int)sv.x; s1 = (int)sv.y; d0 = (int)dv.x; d1 = (int)dv.y;
        } else {
            const int* p = (const int*)ei;
            int2 sv = ((const int2*)p)[idx];
            int2 dv = ((const int2*)(p + N_EDGES))[idx];
            s0 = sv.x; s1 = sv.y; d0 = dv.x; d1 = dv.y;
        }
        int2 r = ((const int2*)g_rank)[idx];
        g_csr_src[g_off[d0] + r.x] = s0;
        g_csr_src[g_off[d1] + r.y] = s1;
    } else {
        int n = idx - NE2;
        g_csr_src[g_off[n]] = n;     // self loop, rank 0
    }
}

// ================= fp16 GEMM, cp.async pipeline, fused attdot ================
#define GBM 128
#define GBN 128
#define GKF 64
#define SBUF 16384
#define GEMM_K 256

template <int LAYER>
__global__ __launch_bounds__(256, 2) void gemm_kernel(
    int M, int Nc,
    const float* __restrict__ att_s_full, const float* __restrict__ att_d_full)
{
    const __half* Ah = (LAYER == 1) ? g_xh  : g_o1h;
    const __half* Bh = (LAYER == 1) ? g_w1h : g_w2h;
    __half* Ch = (LAYER == 1) ? g_h1h : g_h2h;
    float* a_s = (LAYER == 1) ? g_as1 : g_as2;
    float* a_d = (LAYER == 1) ? g_ad1 : g_ad2;
    constexpr int H = (LAYER == 1) ? 2 : 1;

    __shared__ __align__(16) char sA[2 * SBUF];
    __shared__ __align__(16) char sB[2 * SBUF];
    uint32_t sAu = (uint32_t)__cvta_generic_to_shared(sA);
    uint32_t sBu = (uint32_t)__cvta_generic_to_shared(sB);

    const int tid = threadIdx.x;
    const int lane = tid & 31, wid = tid >> 5;
    const int wm = wid & 1, wn = wid >> 1;
    const int bm = blockIdx.x * GBM;
    const int bn = blockIdx.y * GBN;

    float acc[4][4][4];
    #pragma unroll
    for (int i = 0; i < 4; i++)
        #pragma unroll
        for (int j = 0; j < 4; j++)
            #pragma unroll
            for (int r = 0; r < 4; r++) acc[i][j][r] = 0.f;

    const int crow = tid >> 1;
    const int chalf = tid & 1;

    auto issue_tile = [&](int kt) {
        uint32_t bo = (uint32_t)(kt & 1) * SBUF;
        int k0 = kt * GKF;
        uint32_t rb = (uint32_t)crow * 128;
        uint32_t co = (uint32_t)chalf * 64;
        {
            int grow = bm + crow;
            int sz = (grow < M) ? 16 : 0;
            const char* pa = (const char*)(Ah + (size_t)grow * GEMM_K + k0) + co;
            #pragma unroll
            for (int s = 0; s < 4; s++)
                cp16(sAu + bo + swz(rb + co + s * 16), pa + s * 16, sz);
        }
        {
            int gbrow = bn + crow;
            const char* pb = (const char*)(Bh + (size_t)gbrow * GEMM_K + k0) + co;
            #pragma unroll
            for (int s = 0; s < 4; s++)
                cp16(sBu + bo + swz(rb + co + s * 16), pb + s * 16, 16);
        }
    };

    const int la_r   = lane & 7;
    const int la_sub = lane >> 3;
    const int lb_sub = (lane >> 3) & 1;

    const int nktiles = GEMM_K / GKF;   // 4
    issue_tile(0); cp_commit();
    issue_tile(1); cp_commit();

    for (int kt = 0; kt < nktiles; kt++) {
        cp_wait1();
        __syncthreads();
        uint32_t bo = (uint32_t)(kt & 1) * SBUF;
        #pragma unroll
        for (int ks = 0; ks < 4; ks++) {
            uint32_t a[4][4], b[4][2];
            #pragma unroll
            for (int mt = 0; mt < 4; mt++) {
                int row = wm * 64 + mt * 16 + la_r + (la_sub & 1) * 8;
                uint32_t cb = (uint32_t)ks * 32 + (la_sub >> 1) * 16;
                uint32_t ad = sAu + bo + swz((uint32_t)row * 128 + cb);
                asm volatile("ldmatrix.sync.aligned.m8n8.x4.shared.b16 {%0,%1,%2,%3}, [%4];"
                             : "=r"(a[mt][0]), "=r"(a[mt][1]), "=r"(a[mt][2]), "=r"(a[mt][3])
                             : "r"(ad));
            }
            #pragma unroll
            for (int nt = 0; nt < 4; nt++) {
                int row = wn * 32 + nt * 8 + la_r;
                uint32_t cb = (uint32_t)ks * 32 + lb_sub * 16;
                uint32_t ad = sBu + bo + swz((uint32_t)row * 128 + cb);
                asm volatile("ldmatrix.sync.aligned.m8n8.x2.shared.b16 {%0,%1}, [%2];"
                             : "=r"(b[nt][0]), "=r"(b[nt][1])
                             : "r"(ad));
            }
            #pragma unroll
            for (int mt = 0; mt < 4; mt++)
                #pragma unroll
                for (int nt = 0; nt < 4; nt++)
                    mma_fp16(acc[mt][nt][0], acc[mt][nt][1], acc[mt][nt][2], acc[mt][nt][3],
                             a[mt][0], a[mt][1], a[mt][2], a[mt][3], b[nt][0], b[nt][1]);
        }
        __syncthreads();
        if (kt + 2 < nktiles) issue_tile(kt + 2);
        cp_commit();
    }

    // ---- epilogue: fp16 C + fused attention dots ----
    const int g = lane >> 2, tg = lane & 3;

    #pragma unroll
    for (int mt = 0; mt < 4; mt++) {
        int r0 = bm + wm * 64 + mt * 16 + g;
        int r1 = r0 + 8;
        #pragma unroll
        for (int nt = 0; nt < 4; nt++) {
            int col = bn + wn * 32 + nt * 8 + tg * 2;
            if (r0 < M)
                *(__half2*)&Ch[(size_t)r0 * Nc + col] =
                    __floats2half2_rn(acc[mt][nt][0], acc[mt][nt][1]);
            if (r1 < M)
                *(__half2*)&Ch[(size_t)r1 * Nc + col] =
                    __floats2half2_rn(acc[mt][nt][2], acc[mt][nt][3]);
        }
    }

    float2 asv[4], adv[4];
    #pragma unroll
    for (int nt = 0; nt < 4; nt++) {
        int col = bn + wn * 32 + nt * 8 + tg * 2;
        asv[nt] = *(const float2*)&att_s_full[col];
        adv[nt] = *(const float2*)&att_d_full[col];
    }
    float ssr0[4], ssr1[4], sdr0[4], sdr1[4];
    #pragma unroll
    for (int mt = 0; mt < 4; mt++) {
        float s0 = 0.f, s1 = 0.f, d0 = 0.f, d1 = 0.f;
        #pragma unroll
        for (int nt = 0; nt < 4; nt++) {
            s0 += asv[nt].x * acc[mt][nt][0] + asv[nt].y * acc[mt][nt][1];
            s1 += asv[nt].x * acc[mt][nt][2] + asv[nt].y * acc[mt][nt][3];
            d0 += adv[nt].x * acc[mt][nt][0] + adv[nt].y * acc[mt][nt][1];
            d1 += adv[nt].x * acc[mt][nt][2] + adv[nt].y * acc[mt][nt][3];
        }
        #pragma unroll
        for (int o = 1; o <= 2; o <<= 1) {
            s0 += __shfl_xor_sync(0xffffffffu, s0, o);
            s1 += __shfl_xor_sync(0xffffffffu, s1, o);
            d0 += __shfl_xor_sync(0xffffffffu, d0, o);
            d1 += __shfl_xor_sync(0xffffffffu, d1, o);
        }
        ssr0[mt] = s0; ssr1[mt] = s1; sdr0[mt] = d0; sdr1[mt] = d1;
    }
    __syncthreads();
    float* red = (float*)sA;
    if (tg == 0) {
        #pragma unroll
        for (int mt = 0; mt < 4; mt++) {
            int rl0 = wm * 64 + mt * 16 + g;
            red[wn * 128 + rl0]           = ssr0[mt];
            red[wn * 128 + rl0 + 8]       = ssr1[mt];
            red[512 + wn * 128 + rl0]     = sdr0[mt];
            red[512 + wn * 128 + rl0 + 8] = sdr1[mt];
        }
    }
    __syncthreads();
    if (tid < 128) {
        int row = tid;
        float ss = red[row] + red[128 + row] + red[256 + row] + red[384 + row];
        float sd = red[512 + row] + red[640 + row] + red[768 + row] + red[896 + row];
        int grow = bm + row;
        if (grow < M) {
            int head = (H == 2) ? (int)blockIdx.y : 0;
            a_s[grow * H + head] = ss;
            a_d[grow * H + head] = sd;
        }
    }
}

// ---- warp-autonomous fused aggregation: no barriers, no smem ---------------
// One warp per (node, 64-feature slice). Per 32-edge chunk: each lane gathers
// its own (src, e); inner unrolled loop shuffles (e, src) and issues up to 32
// independent coalesced 128B row-segment loads.
template <int LAYER, int H, int C, int WARPS>
__global__ void aggregate_kernel(const float* __restrict__ bias,
                                 float* __restrict__ out_param)
{
    constexpr int HC = H * C;
    const __half* hfeat = (LAYER == 1) ? g_h1h : g_h2h;
    const float* a_s    = (LAYER == 1) ? g_as1 : g_as2;
    const float* a_d    = (LAYER == 1) ? g_ad1 : g_ad2;

    int n = blockIdx.x;
    int warp = threadIdx.x >> 5;
    int lane = threadIdx.x & 31;
    int f = warp * 64 + 2 * lane;          // this lane's feature pair
    int head = f / C;                      // uniform within warp
    int s0 = g_off[n], s1 = g_off[n + 1];
    float adv = a_d[n * H + head];

    float ax = 0.f, ay = 0.f, wsum = 0.f;

    for (int j0 = s0; j0 < s1; j0 += 32) {
        int jj = j0 + lane;
        int src = 0;
        float e = 0.f;
        if (jj < s1) {
            src = g_csr_src[jj];
            float l = a_s[src * H + head] + adv;
            l = l > 0.f ? l : 0.2f * l;
            e = __expf(l);
        }
        wsum += e;
        int cnt = min(32, s1 - j0);
        #pragma unroll
        for (int i = 0; i < 32; i++) {
            if (i >= cnt) break;
            float ei = __shfl_sync(0xffffffffu, e, i);
            int   si = __shfl_sync(0xffffffffu, src, i);
            float2 v = __half22float2(*(const __half2*)&hfeat[(size_t)si * HC + f]);
            ax += ei * v.x;
            ay += ei * v.y;
        }
    }

    #pragma unroll
    for (int o = 16; o; o >>= 1)
        wsum += __shfl_xor_sync(0xffffffffu, wsum, o);

    float iv = 1.f / wsum;
    float ox = ax * iv + bias[f];
    float oy = ay * iv + bias[f + 1];
    if (LAYER == 1) {
        ox = ox > 0.f ? ox : 0.f;
        oy = oy > 0.f ? oy : 0.f;
        *(__half2*)&g_o1h[(size_t)n * HC + f] = __floats2half2_rn(ox, oy);
    } else {
        *(float2*)&out_param[(size_t)n * HC + f] = make_float2(ox, oy);
    }
}

// ---------------- launch ----------------
extern "C" void kernel_launch(void* const* d_in, const int* in_sizes, int n_in,
                              void* d_out, int out_size)
{
    const float* x   = (const float*)d_in[0];
    const void*  ei  = d_in[1];
    const float* W1  = (const float*)d_in[2];
    const float* as1 = (const float*)d_in[3];
    const float* ad1 = (const float*)d_in[4];
    const float* b1  = (const float*)d_in[5];
    const float* W2  = (const float*)d_in[6];
    const float* as2 = (const float*)d_in[7];
    const float* ad2 = (const float*)d_in[8];
    const float* b2  = (const float*)d_in[9];
    float* out = (float*)d_out;

    static cudaStream_t s_side = nullptr;
    static cudaEvent_t  s_evFork = nullptr, s_evCSR = nullptr;
    if (!s_side) {
        cudaStreamCreateWithFlags(&s_side, cudaStreamNonBlocking);
        cudaEventCreateWithFlags(&s_evFork, cudaEventDisableTiming);
        cudaEventCreateWithFlags(&s_evCSR,  cudaEventDisableTiming);
    }

    // prep (main)
    prep_kernel<<<(N_NODES * 256 / 4 + 255) / 256, 256>>>(x, W1, W2, (const int*)ei);

    // fork: CSR chain (side) ∥ gemm1 (main)
    cudaEventRecord(s_evFork, 0);
    cudaStreamWaitEvent(s_side, s_evFork, 0);

    hist_kernel<<<(NE4 + 255) / 256, 256, 0, s_side>>>(ei);
    scan_kernel<<<NB, 256, 0, s_side>>>();
    scatter_kernel<<<(SCAT_T + 255) / 256, 256, 0, s_side>>>(ei);
    cudaEventRecord(s_evCSR, s_side);

    gemm_kernel<1><<<dim3((N_NODES + 127) / 128, 2), 256>>>(N_NODES, 256, as1, ad1);

    // join: aggregate1 needs both gemm1 (main) and CSR (side)
    cudaStreamWaitEvent(0, s_evCSR, 0);

    aggregate_kernel<1, 2, 128, 4><<<N_NODES, 128>>>(b1, nullptr);

    // Layer 2 (sequential dependencies)
    gemm_kernel<2><<<dim3((N_NODES + 127) / 128, 1), 256>>>(N_NODES, 128, as2, ad2);
    aggregate_kernel<2, 1, 128, 2><<<N_NODES, 64>>>(b2, out);
}

// round 16
// speedup vs baseline: 1.1517x; 1.1517x over previous
#include <cuda_runtime.h>
#include <cuda_fp16.h>
#include <cstdint>

#define N_NODES 50000
#define N_EDGES 800000
#define EN      (N_EDGES + N_NODES)
#define NB      ((N_NODES + 255) / 256)
#define NE2     (N_EDGES / 2)
#define NE4     (N_EDGES / 4)

// ---------------- scratch (device globals; no allocation) ----------------
__device__ __half g_xh[(size_t)N_NODES * 256];   // x fp16
__device__ __half g_w1h[256 * 256];              // W1 fp16
__device__ __half g_w2h[128 * 256];              // W2 fp16
__device__ __half g_o1h[(size_t)N_NODES * 256];  // layer1 GAT out fp16
__device__ __half g_h1h[(size_t)N_NODES * 256];  // layer1 linear out fp16
__device__ __half g_h2h[(size_t)N_NODES * 128];  // layer2 linear out fp16
__device__ float  g_as1[N_NODES * 2];
__device__ float  g_ad1[N_NODES * 2];
__device__ float  g_as2[N_NODES];
__device__ float  g_ad2[N_NODES];
__device__ int    g_deg[N_NODES + 8];
__device__ int    g_off[N_NODES + 8];
__device__ int    g_rank[N_EDGES];
__device__ int    g_csr_src[EN];
__device__ int    g_is64;
__device__ unsigned long long g_state[NB + 8];   // decoupled-lookback scan state

// ---------------- helpers ----------------
__device__ __forceinline__ uint32_t swz(uint32_t b) { return b ^ ((b >> 3) & 0x70); }

__device__ __forceinline__ uint32_t pack_h2(__half a, __half b) {
    __half2 t(a, b);
    return *reinterpret_cast<uint32_t*>(&t);
}

__device__ __forceinline__ void cp16(uint32_t dst, const void* src, int sz) {
    asm volatile("cp.async.cg.shared.global [%0], [%1], 16, %2;\n"
                 :: "r"(dst), "l"(src), "r"(sz) : "memory");
}
__device__ __forceinline__ void cp_commit() {
    asm volatile("cp.async.commit_group;\n" ::: "memory");
}
__device__ __forceinline__ void cp_wait1() {
    asm volatile("cp.async.wait_group 1;\n" ::: "memory");
}

__device__ __forceinline__ void mma_fp16(float& c0, float& c1, float& c2, float& c3,
                                         uint32_t a0, uint32_t a1, uint32_t a2, uint32_t a3,
                                         uint32_t b0, uint32_t b1) {
    asm volatile(
        "mma.sync.aligned.m16n8k16.row.col.f32.f16.f16.f32 "
        "{%0,%1,%2,%3}, {%4,%5,%6,%7}, {%8,%9}, {%0,%1,%2,%3};\n"
        : "+f"(c0), "+f"(c1), "+f"(c2), "+f"(c3)
        : "r"(a0), "r"(a1), "r"(a2), "r"(a3), "r"(b0), "r"(b1));
}

__device__ __forceinline__ uint2 cvt4h(float4 v) {
    return make_uint2(pack_h2(__float2half_rn(v.x), __float2half_rn(v.y)),
                      pack_h2(__float2half_rn(v.z), __float2half_rn(v.w)));
}

// ------- prep: x/W fp16 convert + deg init + scan-state zero + dtype detect -------
__global__ void prep_kernel(const float* __restrict__ x,
                            const float* __restrict__ W1src,
                            const float* __restrict__ W2src,
                            const int* __restrict__ ei_w) {
    int i = blockIdx.x * blockDim.x + threadIdx.x;
    const int n4 = N_NODES * 256 / 4;
    const int n1 = 256 * 256 / 4;
    const int n2 = 128 * 256 / 4;
    if (blockIdx.x == 0) {
        if (threadIdx.x == 0) g_is64 = 1;
        __syncthreads();
        if (ei_w[2 * threadIdx.x + 1] != 0) atomicAnd(&g_is64, 0);
    }
    if (i < N_NODES) g_deg[i] = 1;      // self loop
    if (i < NB + 8) g_state[i] = 0ULL;  // scan state reset
    if (i < n1) ((uint2*)g_w1h)[i] = cvt4h(((const float4*)W1src)[i]);
    else if (i < n1 + n2) {
        int idx = i - n1;
        ((uint2*)g_w2h)[idx] = cvt4h(((const float4*)W2src)[idx]);
    }
    if (i < n4) ((uint2*)g_xh)[i] = cvt4h(((const float4*)x)[i]);
}

// ---------------- CSR build ----------------
// histogram + per-edge rank: rank = old count (self loop holds rank 0)
__global__ void hist_kernel(const void* __restrict__ ei) {
    int idx = blockIdx.x * blockDim.x + threadIdx.x;
    if (idx >= NE4) return;
    int d0, d1, d2, d3;
    if (g_is64) {
        const longlong2* p = (const longlong2*)((const long long*)ei + N_EDGES);
        longlong2 a = p[2 * idx], b = p[2 * idx + 1];
        d0 = (int)a.x; d1 = (int)a.y; d2 = (int)b.x; d3 = (int)b.y;
    } else {
        const int4* p = (const int4*)((const int*)ei + N_EDGES);
        int4 d = p[idx];
        d0 = d.x; d1 = d.y; d2 = d.z; d3 = d.w;
    }
    int4 r;
    r.x = atomicAdd(&g_deg[d0], 1);
    r.y = atomicAdd(&g_deg[d1], 1);
    r.z = atomicAdd(&g_deg[d2], 1);
    r.w = atomicAdd(&g_deg[d3], 1);
    ((int4*)g_rank)[idx] = r;
}

// single-pass exclusive scan with decoupled lookback
__global__ void scan_kernel() {
    __shared__ int wsum[8];
    __shared__ int s_prefix;
    int b = blockIdx.x, t = threadIdx.x, lane = t & 31, wid = t >> 5;
    int i = b * 256 + t;
    int v = (i < N_NODES) ? g_deg[i] : 0;
    int x = v;
    #pragma unroll
    for (int o = 1; o < 32; o <<= 1) {
        int y = __shfl_up_sync(0xffffffffu, x, o);
        if (lane >= o) x += y;
    }
    if (lane == 31) wsum[wid] = x;
    __syncthreads();
    if (wid == 0 && lane < 8) {
        int ws = wsum[lane];
        #pragma unroll
        for (int o = 1; o < 8; o <<= 1) {
            int y = __shfl_up_sync(0xffu, ws, o);
            if (lane >= o) ws += y;
        }
        wsum[lane] = ws;
    }
    __syncthreads();
    int incl = x + (wid ? wsum[wid - 1] : 0);
    int btotal = wsum[7];

    if (t == 0) {
        if (b == 0) {
            atomicExch(&g_state[0], (2ULL << 32) | (unsigned)btotal);
            s_prefix = 0;
        } else {
            atomicExch(&g_state[b], (1ULL << 32) | (unsigned)btotal);
            int excl = 0;
            int p = b - 1;
            while (true) {
                unsigned long long s = atomicAdd(&g_state[p], 0ULL);
                unsigned fl = (unsigned)(s >> 32);
                if (fl == 2u) { excl += (int)(unsigned)s; break; }
                if (fl == 1u) { excl += (int)(unsigned)s; p--; }
            }
            atomicExch(&g_state[b], (2ULL << 32) | (unsigned)(excl + btotal));
            s_prefix = excl;
        }
    }
    __syncthreads();
    int e = s_prefix + incl - v;
    if (i < N_NODES) g_off[i] = e;
    if (i == 0) g_off[N_NODES] = EN;
}

// atomic-free scatter: pos = off[dst] + rank[e]; self loops at rank 0
#define SCAT_T (NE2 + N_NODES)
__global__ void scatter_kernel(const void* __restrict__ ei) {
    int idx = blockIdx.x * blockDim.x + threadIdx.x;
    if (idx >= SCAT_T) return;
    if (idx < NE2) {
        int s0, d0, s1, d1;
        if (g_is64) {
            const long long* p = (const long long*)ei;
            const longlong2* ps = (const longlong2*)p;
            const longlong2* pd = (const longlong2*)(p + N_EDGES);
            longlong2 sv = ps[idx], dv = pd[idx];
            s0 = (int)sv.x; s1 = (int)sv.y; d0 = (int)dv.x; d1 = (int)dv.y;
        } else {
            const int* p = (const int*)ei;
            int2 sv = ((const int2*)p)[idx];
            int2 dv = ((const int2*)(p + N_EDGES))[idx];
            s0 = sv.x; s1 = sv.y; d0 = dv.x; d1 = dv.y;
        }
        int2 r = ((const int2*)g_rank)[idx];
        g_csr_src[g_off[d0] + r.x] = s0;
        g_csr_src[g_off[d1] + r.y] = s1;
    } else {
        int n = idx - NE2;
        g_csr_src[g_off[n]] = n;     // self loop, rank 0
    }
}

// ================= fp16 GEMM, cp.async pipeline, fused attdot ================
#define GBM 128
#define GBN 128
#define GKF 64
#define SBUF 16384
#define GEMM_K 256

template <int LAYER>
__global__ __launch_bounds__(256, 2) void gemm_kernel(
    int M, int Nc,
    const float* __restrict__ att_s_full, const float* __restrict__ att_d_full)
{
    const __half* Ah = (LAYER == 1) ? g_xh  : g_o1h;
    const __half* Bh = (LAYER == 1) ? g_w1h : g_w2h;
    __half* Ch = (LAYER == 1) ? g_h1h : g_h2h;
    float* a_s = (LAYER == 1) ? g_as1 : g_as2;
    float* a_d = (LAYER == 1) ? g_ad1 : g_ad2;
    constexpr int H = (LAYER == 1) ? 2 : 1;

    __shared__ __align__(16) char sA[2 * SBUF];
    __shared__ __align__(16) char sB[2 * SBUF];
    uint32_t sAu = (uint32_t)__cvta_generic_to_shared(sA);
    uint32_t sBu = (uint32_t)__cvta_generic_to_shared(sB);

    const int tid = threadIdx.x;
    const int lane = tid & 31, wid = tid >> 5;
    const int wm = wid & 1, wn = wid >> 1;
    const int bm = blockIdx.x * GBM;
    const int bn = blockIdx.y * GBN;

    float acc[4][4][4];
    #pragma unroll
    for (int i = 0; i < 4; i++)
        #pragma unroll
        for (int j = 0; j < 4; j++)
            #pragma unroll
            for (int r = 0; r < 4; r++) acc[i][j][r] = 0.f;

    const int crow = tid >> 1;
    const int chalf = tid & 1;

    auto issue_tile = [&](int kt) {
        uint32_t bo = (uint32_t)(kt & 1) * SBUF;
        int k0 = kt * GKF;
        uint32_t rb = (uint32_t)crow * 128;
        uint32_t co = (uint32_t)chalf * 64;
        {
            int grow = bm + crow;
            int sz = (grow < M) ? 16 : 0;
            const char* pa = (const char*)(Ah + (size_t)grow * GEMM_K + k0) + co;
            #pragma unroll
            for (int s = 0; s < 4; s++)
                cp16(sAu + bo + swz(rb + co + s * 16), pa + s * 16, sz);
        }
        {
            int gbrow = bn + crow;
            const char* pb = (const char*)(Bh + (size_t)gbrow * GEMM_K + k0) + co;
            #pragma unroll
            for (int s = 0; s < 4; s++)
                cp16(sBu + bo + swz(rb + co + s * 16), pb + s * 16, 16);
        }
    };

    const int la_r   = lane & 7;
    const int la_sub = lane >> 3;
    const int lb_sub = (lane >> 3) & 1;

    const int nktiles = GEMM_K / GKF;   // 4
    issue_tile(0); cp_commit();
    issue_tile(1); cp_commit();

    for (int kt = 0; kt < nktiles; kt++) {
        cp_wait1();
        __syncthreads();
        uint32_t bo = (uint32_t)(kt & 1) * SBUF;
        #pragma unroll
        for (int ks = 0; ks < 4; ks++) {
            uint32_t a[4][4], b[4][2];
            #pragma unroll
            for (int mt = 0; mt < 4; mt++) {
                int row = wm * 64 + mt * 16 + la_r + (la_sub & 1) * 8;
                uint32_t cb = (uint32_t)ks * 32 + (la_sub >> 1) * 16;
                uint32_t ad = sAu + bo + swz((uint32_t)row * 128 + cb);
                asm volatile("ldmatrix.sync.aligned.m8n8.x4.shared.b16 {%0,%1,%2,%3}, [%4];"
                             : "=r"(a[mt][0]), "=r"(a[mt][1]), "=r"(a[mt][2]), "=r"(a[mt][3])
                             : "r"(ad));
            }
            #pragma unroll
            for (int nt = 0; nt < 4; nt++) {
                int row = wn * 32 + nt * 8 + la_r;
                uint32_t cb = (uint32_t)ks * 32 + lb_sub * 16;
                uint32_t ad = sBu + bo + swz((uint32_t)row * 128 + cb);
                asm volatile("ldmatrix.sync.aligned.m8n8.x2.shared.b16 {%0,%1}, [%2];"
                             : "=r"(b[nt][0]), "=r"(b[nt][1])
                             : "r"(ad));
            }
            #pragma unroll
            for (int mt = 0; mt < 4; mt++)
                #pragma unroll
                for (int nt = 0; nt < 4; nt++)
                    mma_fp16(acc[mt][nt][0], acc[mt][nt][1], acc[mt][nt][2], acc[mt][nt][3],
                             a[mt][0], a[mt][1], a[mt][2], a[mt][3], b[nt][0], b[nt][1]);
        }
        __syncthreads();
        if (kt + 2 < nktiles) issue_tile(kt + 2);
        cp_commit();
    }

    // ---- epilogue: fp16 C + fused attention dots ----
    const int g = lane >> 2, tg = lane & 3;

    #pragma unroll
    for (int mt = 0; mt < 4; mt++) {
        int r0 = bm + wm * 64 + mt * 16 + g;
        int r1 = r0 + 8;
        #pragma unroll
        for (int nt = 0; nt < 4; nt++) {
            int col = bn + wn * 32 + nt * 8 + tg * 2;
            if (r0 < M)
                *(__half2*)&Ch[(size_t)r0 * Nc + col] =
                    __floats2half2_rn(acc[mt][nt][0], acc[mt][nt][1]);
            if (r1 < M)
                *(__half2*)&Ch[(size_t)r1 * Nc + col] =
                    __floats2half2_rn(acc[mt][nt][2], acc[mt][nt][3]);
        }
    }

    float2 asv[4], adv[4];
    #pragma unroll
    for (int nt = 0; nt < 4; nt++) {
        int col = bn + wn * 32 + nt * 8 + tg * 2;
        asv[nt] = *(const float2*)&att_s_full[col];
        adv[nt] = *(const float2*)&att_d_full[col];
    }
    float ssr0[4], ssr1[4], sdr0[4], sdr1[4];
    #pragma unroll
    for (int mt = 0; mt < 4; mt++) {
        float s0 = 0.f, s1 = 0.f, d0 = 0.f, d1 = 0.f;
        #pragma unroll
        for (int nt = 0; nt < 4; nt++) {
            s0 += asv[nt].x * acc[mt][nt][0] + asv[nt].y * acc[mt][nt][1];
            s1 += asv[nt].x * acc[mt][nt][2] + asv[nt].y * acc[mt][nt][3];
            d0 += adv[nt].x * acc[mt][nt][0] + adv[nt].y * acc[mt][nt][1];
            d1 += adv[nt].x * acc[mt][nt][2] + adv[nt].y * acc[mt][nt][3];
        }
        #pragma unroll
        for (int o = 1; o <= 2; o <<= 1) {
            s0 += __shfl_xor_sync(0xffffffffu, s0, o);
            s1 += __shfl_xor_sync(0xffffffffu, s1, o);
            d0 += __shfl_xor_sync(0xffffffffu, d0, o);
            d1 += __shfl_xor_sync(0xffffffffu, d1, o);
        }
        ssr0[mt] = s0; ssr1[mt] = s1; sdr0[mt] = d0; sdr1[mt] = d1;
    }
    __syncthreads();
    float* red = (float*)sA;
    if (tg == 0) {
        #pragma unroll
        for (int mt = 0; mt < 4; mt++) {
            int rl0 = wm * 64 + mt * 16 + g;
            red[wn * 128 + rl0]           = ssr0[mt];
            red[wn * 128 + rl0 + 8]       = ssr1[mt];
            red[512 + wn * 128 + rl0]     = sdr0[mt];
            red[512 + wn * 128 + rl0 + 8] = sdr1[mt];
        }
    }
    __syncthreads();
    if (tid < 128) {
        int row = tid;
        float ss = red[row] + red[128 + row] + red[256 + row] + red[384 + row];
        float sd = red[512 + row] + red[640 + row] + red[768 + row] + red[896 + row];
        int grow = bm + row;
        if (grow < M) {
            int head = (H == 2) ? (int)blockIdx.y : 0;
            a_s[grow * H + head] = ss;
            a_d[grow * H + head] = sd;
        }
    }
}

// ---- fused aggregation: softmax weights computed in-block, one pass --------
template <int LAYER, int H, int C>
__global__ void aggregate_kernel(const float* __restrict__ bias,
                                 float* __restrict__ out_param)
{
    constexpr int HC = H * C;
    constexpr int CH = HC / 2;    // == blockDim
    const __half* hfeat = (LAYER == 1) ? g_h1h : g_h2h;
    const float* a_s    = (LAYER == 1) ? g_as1 : g_as2;
    const float* a_d    = (LAYER == 1) ? g_ad1 : g_ad2;

    __shared__ int   s_src[CH];
    __shared__ float s_e[H * CH];

    int n = blockIdx.x;
    int t = threadIdx.x;
    int f = 2 * t;
    int head = f / C;
    int s0 = g_off[n], s1 = g_off[n + 1];

    float adv[H];
    #pragma unroll
    for (int h = 0; h < H; h++) adv[h] = a_d[n * H + h];

    float ax = 0.f, ay = 0.f, wsum = 0.f;

    for (int j0 = s0; j0 < s1; j0 += CH) {
        int cnt = min(CH, s1 - j0);
        if (t < cnt) {
            int src = g_csr_src[j0 + t];
            s_src[t] = src;
            #pragma unroll
            for (int h = 0; h < H; h++) {
                float l = a_s[src * H + h] + adv[h];
                l = l > 0.f ? l : 0.2f * l;
                s_e[h * CH + t] = __expf(l);
            }
        }
        __syncthreads();
        const float* eh = &s_e[head * CH];
        int i = 0;
        for (; i + 7 < cnt; i += 8) {
            int sr0 = s_src[i],     sr1 = s_src[i + 1], sr2 = s_src[i + 2], sr3 = s_src[i + 3];
            int sr4 = s_src[i + 4], sr5 = s_src[i + 5], sr6 = s_src[i + 6], sr7 = s_src[i + 7];
            float e0 = eh[i],     e1 = eh[i + 1], e2 = eh[i + 2], e3 = eh[i + 3];
            float e4 = eh[i + 4], e5 = eh[i + 5], e6 = eh[i + 6], e7 = eh[i + 7];
            float2 v0 = __half22float2(*(const __half2*)&hfeat[(size_t)sr0 * HC + f]);
            float2 v1 = __half22float2(*(const __half2*)&hfeat[(size_t)sr1 * HC + f]);
            float2 v2 = __half22float2(*(const __half2*)&hfeat[(size_t)sr2 * HC + f]);
            float2 v3 = __half22float2(*(const __half2*)&hfeat[(size_t)sr3 * HC + f]);
            float2 v4 = __half22float2(*(const __half2*)&hfeat[(size_t)sr4 * HC + f]);
            float2 v5 = __half22float2(*(const __half2*)&hfeat[(size_t)sr5 * HC + f]);
            float2 v6 = __half22float2(*(const __half2*)&hfeat[(size_t)sr6 * HC + f]);
            float2 v7 = __half22float2(*(const __half2*)&hfeat[(size_t)sr7 * HC + f]);
            ax += e0 * v0.x + e1 * v1.x + e2 * v2.x + e3 * v3.x
                + e4 * v4.x + e5 * v5.x + e6 * v6.x + e7 * v7.x;
            ay += e0 * v0.y + e1 * v1.y + e2 * v2.y + e3 * v3.y
                + e4 * v4.y + e5 * v5.y + e6 * v6.y + e7 * v7.y;
            wsum += ((e0 + e1) + (e2 + e3)) + ((e4 + e5) + (e6 + e7));
        }
        for (; i + 3 < cnt; i += 4) {
            int sr0 = s_src[i], sr1 = s_src[i + 1], sr2 = s_src[i + 2], sr3 = s_src[i + 3];
            float e0 = eh[i], e1 = eh[i + 1], e2 = eh[i + 2], e3 = eh[i + 3];
            float2 v0 = __half22float2(*(const __half2*)&hfeat[(size_t)sr0 * HC + f]);
            float2 v1 = __half22float2(*(const __half2*)&hfeat[(size_t)sr1 * HC + f]);
            float2 v2 = __half22float2(*(const __half2*)&hfeat[(size_t)sr2 * HC + f]);
            float2 v3 = __half22float2(*(const __half2*)&hfeat[(size_t)sr3 * HC + f]);
            ax += e0 * v0.x + e1 * v1.x + e2 * v2.x + e3 * v3.x;
            ay += e0 * v0.y + e1 * v1.y + e2 * v2.y + e3 * v3.y;
            wsum += (e0 + e1) + (e2 + e3);
        }
        for (; i < cnt; i++) {
            int sr = s_src[i];
            float e = eh[i];
            float2 v = __half22float2(*(const __half2*)&hfeat[(size_t)sr * HC + f]);
            ax += e * v.x;
            ay += e * v.y;
            wsum += e;
        }
        if (j0 + CH < s1) __syncthreads();   // barrier only if another chunk follows
    }

    float iv = 1.f / wsum;
    float ox = ax * iv + bias[f];
    float oy = ay * iv + bias[f + 1];
    if (LAYER == 1) {
        ox = ox > 0.f ? ox : 0.f;
        oy = oy > 0.f ? oy : 0.f;
        *(__half2*)&g_o1h[(size_t)n * HC + f] = __floats2half2_rn(ox, oy);
    } else {
        *(float2*)&out_param[(size_t)n * HC + f] = make_float2(ox, oy);
    }
}

// ---------------- launch ----------------
extern "C" void kernel_launch(void* const* d_in, const int* in_sizes, int n_in,
                              void* d_out, int out_size)
{
    const float* x   = (const float*)d_in[0];
    const void*  ei  = d_in[1];
    const float* W1  = (const float*)d_in[2];
    const float* as1 = (const float*)d_in[3];
    const float* ad1 = (const float*)d_in[4];
    const float* b1  = (const float*)d_in[5];
    const float* W2  = (const float*)d_in[6];
    const float* as2 = (const float*)d_in[7];
    const float* ad2 = (const float*)d_in[8];
    const float* b2  = (const float*)d_in[9];
    float* out = (float*)d_out;

    static cudaStream_t s_side = nullptr;
    static cudaEvent_t  s_evFork = nullptr, s_evCSR = nullptr;
    if (!s_side) {
        cudaStreamCreateWithFlags(&s_side, cudaStreamNonBlocking);
        cudaEventCreateWithFlags(&s_evFork, cudaEventDisableTiming);
        cudaEventCreateWithFlags(&s_evCSR,  cudaEventDisableTiming);
    }

    // prep (main)
    prep_kernel<<<(N_NODES * 256 / 4 + 255) / 256, 256>>>(x, W1, W2, (const int*)ei);

    // fork: CSR chain (side) ∥ gemm1 (main)
    cudaEventRecord(s_evFork, 0);
    cudaStreamWaitEvent(s_side, s_evFork, 0);

    hist_kernel<<<(NE4 + 255) / 256, 256, 0, s_side>>>(ei);
    scan_kernel<<<NB, 256, 0, s_side>>>();
    scatter_kernel<<<(SCAT_T + 255) / 256, 256, 0, s_side>>>(ei);
    cudaEventRecord(s_evCSR, s_side);

    gemm_kernel<1><<<dim3((N_NODES + 127) / 128, 2), 256>>>(N_NODES, 256, as1, ad1);

    // join: aggregate1 needs both gemm1 (main) and CSR (side)
    cudaStreamWaitEvent(0, s_evCSR, 0);

    aggregate_kernel<1, 2, 128><<<N_NODES, 128>>>(b1, nullptr);

    // Layer 2 (sequential dependencies)
    gemm_kernel<2><<<dim3((N_NODES + 127) / 128, 1), 256>>>(N_NODES, 128, as2, ad2);
    aggregate_kernel<2, 1, 128><<<N_NODES, 64>>>(b2, out);
}

// round 17
// speedup vs baseline: 1.3425x; 1.1657x over previous
#include <cuda_runtime.h>
#include <cuda_fp16.h>
#include <cstdint>

#define N_NODES 50000
#define N_EDGES 800000
#define EN      (N_EDGES + N_NODES)
#define NB      ((N_NODES + 255) / 256)
#define NE2     (N_EDGES / 2)
#define NE4     (N_EDGES / 4)

// ---------------- scratch (device globals; no allocation) ----------------
__device__ __half g_xh[(size_t)N_NODES * 256];   // x fp16
__device__ __half g_w1h[256 * 256];              // W1 fp16
__device__ __half g_w2h[128 * 256];              // W2 fp16
__device__ __half g_o1h[(size_t)N_NODES * 256];  // layer1 GAT out fp16
__device__ __half g_h1h[(size_t)N_NODES * 256];  // layer1 linear out fp16
__device__ __half g_h2h[(size_t)N_NODES * 128];  // layer2 linear out fp16
__device__ float  g_as1[N_NODES * 2];
__device__ float  g_ad1[N_NODES * 2];
__device__ float  g_as2[N_NODES];
__device__ float  g_ad2[N_NODES];
__device__ int    g_deg[N_NODES + 8];
__device__ int    g_off[N_NODES + 8];
__device__ int    g_rank[N_EDGES];
__device__ int    g_csr_src[EN];
__device__ int    g_is64;
__device__ unsigned long long g_state[NB + 8];   // decoupled-lookback scan state

// ---------------- helpers ----------------
__device__ __forceinline__ uint32_t swz(uint32_t b) { return b ^ ((b >> 3) & 0x70); }

__device__ __forceinline__ uint32_t pack_h2(__half a, __half b) {
    __half2 t(a, b);
    return *reinterpret_cast<uint32_t*>(&t);
}

__device__ __forceinline__ void cp16(uint32_t dst, const void* src, int sz) {
    asm volatile("cp.async.cg.shared.global [%0], [%1], 16, %2;\n"
                 :: "r"(dst), "l"(src), "r"(sz) : "memory");
}
__device__ __forceinline__ void cp_commit() {
    asm volatile("cp.async.commit_group;\n" ::: "memory");
}
__device__ __forceinline__ void cp_wait1() {
    asm volatile("cp.async.wait_group 1;\n" ::: "memory");
}

__device__ __forceinline__ void mma_fp16(float& c0, float& c1, float& c2, float& c3,
                                         uint32_t a0, uint32_t a1, uint32_t a2, uint32_t a3,
                                         uint32_t b0, uint32_t b1) {
    asm volatile(
        "mma.sync.aligned.m16n8k16.row.col.f32.f16.f16.f32 "
        "{%0,%1,%2,%3}, {%4,%5,%6,%7}, {%8,%9}, {%0,%1,%2,%3};\n"
        : "+f"(c0), "+f"(c1), "+f"(c2), "+f"(c3)
        : "r"(a0), "r"(a1), "r"(a2), "r"(a3), "r"(b0), "r"(b1));
}

__device__ __forceinline__ uint2 cvt4h(float4 v) {
    return make_uint2(pack_h2(__float2half_rn(v.x), __float2half_rn(v.y)),
                      pack_h2(__float2half_rn(v.z), __float2half_rn(v.w)));
}

// ------- init: deg + scan-state + dtype detect (side stream, tiny) -------
__global__ void init_kernel(const int* __restrict__ ei_w) {
    int i = blockIdx.x * blockDim.x + threadIdx.x;
    if (blockIdx.x == 0) {
        if (threadIdx.x == 0) g_is64 = 1;
        __syncthreads();
        if (ei_w[2 * threadIdx.x + 1] != 0) atomicAnd(&g_is64, 0);
    }
    if (i < N_NODES) g_deg[i] = 1;      // self loop
    if (i < NB + 8) g_state[i] = 0ULL;  // scan state reset
}

// ------- conv: x/W fp16 convert (main stream, feeds gemm1) -------
__global__ void conv_kernel(const float* __restrict__ x,
                            const float* __restrict__ W1src,
                            const float* __restrict__ W2src) {
    int i = blockIdx.x * blockDim.x + threadIdx.x;
    const int n4 = N_NODES * 256 / 4;
    const int n1 = 256 * 256 / 4;
    const int n2 = 128 * 256 / 4;
    if (i < n1) ((uint2*)g_w1h)[i] = cvt4h(((const float4*)W1src)[i]);
    else if (i < n1 + n2) {
        int idx = i - n1;
        ((uint2*)g_w2h)[idx] = cvt4h(((const float4*)W2src)[idx]);
    }
    if (i < n4) ((uint2*)g_xh)[i] = cvt4h(((const float4*)x)[i]);
}

// ---------------- CSR build ----------------
// histogram + per-edge rank: rank = old count (self loop holds rank 0)
__global__ void hist_kernel(const void* __restrict__ ei) {
    int idx = blockIdx.x * blockDim.x + threadIdx.x;
    if (idx >= NE4) return;
    int d0, d1, d2, d3;
    if (g_is64) {
        const longlong2* p = (const longlong2*)((const long long*)ei + N_EDGES);
        longlong2 a = p[2 * idx], b = p[2 * idx + 1];
        d0 = (int)a.x; d1 = (int)a.y; d2 = (int)b.x; d3 = (int)b.y;
    } else {
        const int4* p = (const int4*)((const int*)ei + N_EDGES);
        int4 d = p[idx];
        d0 = d.x; d1 = d.y; d2 = d.z; d3 = d.w;
    }
    int4 r;
    r.x = atomicAdd(&g_deg[d0], 1);
    r.y = atomicAdd(&g_deg[d1], 1);
    r.z = atomicAdd(&g_deg[d2], 1);
    r.w = atomicAdd(&g_deg[d3], 1);
    ((int4*)g_rank)[idx] = r;
}

// single-pass exclusive scan with decoupled lookback
__global__ void scan_kernel() {
    __shared__ int wsum[8];
    __shared__ int s_prefix;
    int b = blockIdx.x, t = threadIdx.x, lane = t & 31, wid = t >> 5;
    int i = b * 256 + t;
    int v = (i < N_NODES) ? g_deg[i] : 0;
    int x = v;
    #pragma unroll
    for (int o = 1; o < 32; o <<= 1) {
        int y = __shfl_up_sync(0xffffffffu, x, o);
        if (lane >= o) x += y;
    }
    if (lane == 31) wsum[wid] = x;
    __syncthreads();
    if (wid == 0 && lane < 8) {
        int ws = wsum[lane];
        #pragma unroll
        for (int o = 1; o < 8; o <<= 1) {
            int y = __shfl_up_sync(0xffu, ws, o);
            if (lane >= o) ws += y;
        }
        wsum[lane] = ws;
    }
    __syncthreads();
    int incl = x + (wid ? wsum[wid - 1] : 0);
    int btotal = wsum[7];

    if (t == 0) {
        if (b == 0) {
            atomicExch(&g_state[0], (2ULL << 32) | (unsigned)btotal);
            s_prefix = 0;
        } else {
            atomicExch(&g_state[b], (1ULL << 32) | (unsigned)btotal);
            int excl = 0;
            int p = b - 1;
            while (true) {
                unsigned long long s = atomicAdd(&g_state[p], 0ULL);
                unsigned fl = (unsigned)(s >> 32);
                if (fl == 2u) { excl += (int)(unsigned)s; break; }
                if (fl == 1u) { excl += (int)(unsigned)s; p--; }
            }
            atomicExch(&g_state[b], (2ULL << 32) | (unsigned)(excl + btotal));
            s_prefix = excl;
        }
    }
    __syncthreads();
    int e = s_prefix + incl - v;
    if (i < N_NODES) g_off[i] = e;
    if (i == 0) g_off[N_NODES] = EN;
}

// atomic-free scatter: pos = off[dst] + rank[e]; self loops at rank 0
#define SCAT_T (NE2 + N_NODES)
__global__ void scatter_kernel(const void* __restrict__ ei) {
    int idx = blockIdx.x * blockDim.x + threadIdx.x;
    if (idx >= SCAT_T) return;
    if (idx < NE2) {
        int s0, d0, s1, d1;
        if (g_is64) {
            const long long* p = (const long long*)ei;
            const longlong2* ps = (const longlong2*)p;
            const longlong2* pd = (const longlong2*)(p + N_EDGES);
            longlong2 sv = ps[idx], dv = pd[idx];
            s0 = (int)sv.x; s1 = (int)sv.y; d0 = (int)dv.x; d1 = (int)dv.y;
        } else {
            const int* p = (const int*)ei;
            int2 sv = ((const int2*)p)[idx];
            int2 dv = ((const int2*)(p + N_EDGES))[idx];
            s0 = sv.x; s1 = sv.y; d0 = dv.x; d1 = dv.y;
        }
        int2 r = ((const int2*)g_rank)[idx];
        g_csr_src[g_off[d0] + r.x] = s0;
        g_csr_src[g_off[d1] + r.y] = s1;
    } else {
        int n = idx - NE2;
        g_csr_src[g_off[n]] = n;     // self loop, rank 0
    }
}

// ================= fp16 GEMM, cp.async pipeline, fused attdot ================
#define GBM 128
#define GBN 128
#define GKF 64
#define SBUF 16384
#define GEMM_K 256

template <int LAYER>
__global__ __launch_bounds__(256, 2) void gemm_kernel(
    int M, int Nc,
    const float* __restrict__ att_s_full, const float* __restrict__ att_d_full)
{
    const __half* Ah = (LAYER == 1) ? g_xh  : g_o1h;
    const __half* Bh = (LAYER == 1) ? g_w1h : g_w2h;
    __half* Ch = (LAYER == 1) ? g_h1h : g_h2h;
    float* a_s = (LAYER == 1) ? g_as1 : g_as2;
    float* a_d = (LAYER == 1) ? g_ad1 : g_ad2;
    constexpr int H = (LAYER == 1) ? 2 : 1;

    __shared__ __align__(16) char sA[2 * SBUF];
    __shared__ __align__(16) char sB[2 * SBUF];
    uint32_t sAu = (uint32_t)__cvta_generic_to_shared(sA);
    uint32_t sBu = (uint32_t)__cvta_generic_to_shared(sB);

    const int tid = threadIdx.x;
    const int lane = tid & 31, wid = tid >> 5;
    const int wm = wid & 1, wn = wid >> 1;
    const int bm = blockIdx.x * GBM;
    const int bn = blockIdx.y * GBN;

    float acc[4][4][4];
    #pragma unroll
    for (int i = 0; i < 4; i++)
        #pragma unroll
        for (int j = 0; j < 4; j++)
            #pragma unroll
            for (int r = 0; r < 4; r++) acc[i][j][r] = 0.f;

    const int crow = tid >> 1;
    const int chalf = tid & 1;

    auto issue_tile = [&](int kt) {
        uint32_t bo = (uint32_t)(kt & 1) * SBUF;
        int k0 = kt * GKF;
        uint32_t rb = (uint32_t)crow * 128;
        uint32_t co = (uint32_t)chalf * 64;
        {
            int grow = bm + crow;
            int sz = (grow < M) ? 16 : 0;
            const char* pa = (const char*)(Ah + (size_t)grow * GEMM_K + k0) + co;
            #pragma unroll
            for (int s = 0; s < 4; s++)
                cp16(sAu + bo + swz(rb + co + s * 16), pa + s * 16, sz);
        }
        {
            int gbrow = bn + crow;
            const char* pb = (const char*)(Bh + (size_t)gbrow * GEMM_K + k0) + co;
            #pragma unroll
            for (int s = 0; s < 4; s++)
                cp16(sBu + bo + swz(rb + co + s * 16), pb + s * 16, 16);
        }
    };

    const int la_r   = lane & 7;
    const int la_sub = lane >> 3;
    const int lb_sub = (lane >> 3) & 1;

    const int nktiles = GEMM_K / GKF;   // 4
    issue_tile(0); cp_commit();
    issue_tile(1); cp_commit();

    for (int kt = 0; kt < nktiles; kt++) {
        cp_wait1();
        __syncthreads();
        uint32_t bo = (uint32_t)(kt & 1) * SBUF;
        #pragma unroll
        for (int ks = 0; ks < 4; ks++) {
            uint32_t a[4][4], b[4][2];
            #pragma unroll
            for (int mt = 0; mt < 4; mt++) {
                int row = wm * 64 + mt * 16 + la_r + (la_sub & 1) * 8;
                uint32_t cb = (uint32_t)ks * 32 + (la_sub >> 1) * 16;
                uint32_t ad = sAu + bo + swz((uint32_t)row * 128 + cb);
                asm volatile("ldmatrix.sync.aligned.m8n8.x4.shared.b16 {%0,%1,%2,%3}, [%4];"
                             : "=r"(a[mt][0]), "=r"(a[mt][1]), "=r"(a[mt][2]), "=r"(a[mt][3])
                             : "r"(ad));
            }
            #pragma unroll
            for (int nt = 0; nt < 4; nt++) {
                int row = wn * 32 + nt * 8 + la_r;
                uint32_t cb = (uint32_t)ks * 32 + lb_sub * 16;
                uint32_t ad = sBu + bo + swz((uint32_t)row * 128 + cb);
                asm volatile("ldmatrix.sync.aligned.m8n8.x2.shared.b16 {%0,%1}, [%2];"
                             : "=r"(b[nt][0]), "=r"(b[nt][1])
                             : "r"(ad));
            }
            #pragma unroll
            for (int mt = 0; mt < 4; mt++)
                #pragma unroll
                for (int nt = 0; nt < 4; nt++)
                    mma_fp16(acc[mt][nt][0], acc[mt][nt][1], acc[mt][nt][2], acc[mt][nt][3],
                             a[mt][0], a[mt][1], a[mt][2], a[mt][3], b[nt][0], b[nt][1]);
        }
        __syncthreads();
        if (kt + 2 < nktiles) issue_tile(kt + 2);
        cp_commit();
    }

    // ---- epilogue: fp16 C + fused attention dots ----
    const int g = lane >> 2, tg = lane & 3;

    #pragma unroll
    for (int mt = 0; mt < 4; mt++) {
        int r0 = bm + wm * 64 + mt * 16 + g;
        int r1 = r0 + 8;
        #pragma unroll
        for (int nt = 0; nt < 4; nt++) {
            int col = bn + wn * 32 + nt * 8 + tg * 2;
            if (r0 < M)
                *(__half2*)&Ch[(size_t)r0 * Nc + col] =
                    __floats2half2_rn(acc[mt][nt][0], acc[mt][nt][1]);
            if (r1 < M)
                *(__half2*)&Ch[(size_t)r1 * Nc + col] =
                    __floats2half2_rn(acc[mt][nt][2], acc[mt][nt][3]);
        }
    }

    float2 asv[4], adv[4];
    #pragma unroll
    for (int nt = 0; nt < 4; nt++) {
        int col = bn + wn * 32 + nt * 8 + tg * 2;
        asv[nt] = *(const float2*)&att_s_full[col];
        adv[nt] = *(const float2*)&att_d_full[col];
    }
    float ssr0[4], ssr1[4], sdr0[4], sdr1[4];
    #pragma unroll
    for (int mt = 0; mt < 4; mt++) {
        float s0 = 0.f, s1 = 0.f, d0 = 0.f, d1 = 0.f;
        #pragma unroll
        for (int nt = 0; nt < 4; nt++) {
            s0 += asv[nt].x * acc[mt][nt][0] + asv[nt].y * acc[mt][nt][1];
            s1 += asv[nt].x * acc[mt][nt][2] + asv[nt].y * acc[mt][nt][3];
            d0 += adv[nt].x * acc[mt][nt][0] + adv[nt].y * acc[mt][nt][1];
            d1 += adv[nt].x * acc[mt][nt][2] + adv[nt].y * acc[mt][nt][3];
        }
        #pragma unroll
        for (int o = 1; o <= 2; o <<= 1) {
            s0 += __shfl_xor_sync(0xffffffffu, s0, o);
            s1 += __shfl_xor_sync(0xffffffffu, s1, o);
            d0 += __shfl_xor_sync(0xffffffffu, d0, o);
            d1 += __shfl_xor_sync(0xffffffffu, d1, o);
        }
        ssr0[mt] = s0; ssr1[mt] = s1; sdr0[mt] = d0; sdr1[mt] = d1;
    }
    __syncthreads();
    float* red = (float*)sA;
    if (tg == 0) {
        #pragma unroll
        for (int mt = 0; mt < 4; mt++) {
            int rl0 = wm * 64 + mt * 16 + g;
            red[wn * 128 + rl0]           = ssr0[mt];
            red[wn * 128 + rl0 + 8]       = ssr1[mt];
            red[512 + wn * 128 + rl0]     = sdr0[mt];
            red[512 + wn * 128 + rl0 + 8] = sdr1[mt];
        }
    }
    __syncthreads();
    if (tid < 128) {
        int row = tid;
        float ss = red[row] + red[128 + row] + red[256 + row] + red[384 + row];
        float sd = red[512 + row] + red[640 + row] + red[768 + row] + red[896 + row];
        int grow = bm + row;
        if (grow < M) {
            int head = (H == 2) ? (int)blockIdx.y : 0;
            a_s[grow * H + head] = ss;
            a_d[grow * H + head] = sd;
        }
    }
}

// ---- fused aggregation: one thread per 4 features (uint2 gathers) ----------
template <int LAYER, int H, int C>
__global__ void aggregate_kernel(const float* __restrict__ bias,
                                 float* __restrict__ out_param)
{
    constexpr int HC = H * C;
    constexpr int CH = HC / 4;    // == blockDim (64 for L1, 32 for L2)
    const __half* hfeat = (LAYER == 1) ? g_h1h : g_h2h;
    const float* a_s    = (LAYER == 1) ? g_as1 : g_as2;
    const float* a_d    = (LAYER == 1) ? g_ad1 : g_ad2;

    __shared__ int   s_src[CH];
    __shared__ float s_e[H * CH];

    int n = blockIdx.x;
    int t = threadIdx.x;
    int f = 4 * t;
    int head = f / C;
    int s0 = g_off[n], s1 = g_off[n + 1];

    float adv[H];
    #pragma unroll
    for (int h = 0; h < H; h++) adv[h] = a_d[n * H + h];

    float ax = 0.f, ay = 0.f, az = 0.f, aw = 0.f, wsum = 0.f;

    for (int j0 = s0; j0 < s1; j0 += CH) {
        int cnt = min(CH, s1 - j0);
        if (t < cnt) {
            int src = g_csr_src[j0 + t];
            s_src[t] = src;
            #pragma unroll
            for (int h = 0; h < H; h++) {
                float l = a_s[src * H + h] + adv[h];
                l = l > 0.f ? l : 0.2f * l;
                s_e[h * CH + t] = __expf(l);
            }
        }
        __syncthreads();
        const float* eh = &s_e[head * CH];
        int i = 0;
        for (; i + 7 < cnt; i += 8) {
            #pragma unroll
            for (int u = 0; u < 8; u++) {
                int sr = s_src[i + u];
                float e = eh[i + u];
                uint2 q = *(const uint2*)&hfeat[(size_t)sr * HC + f];
                float2 v0 = __half22float2(*(__half2*)&q.x);
                float2 v1 = __half22float2(*(__half2*)&q.y);
                ax += e * v0.x; ay += e * v0.y;
                az += e * v1.x; aw += e * v1.y;
                wsum += e;
            }
        }
        for (; i < cnt; i++) {
            int sr = s_src[i];
            float e = eh[i];
            uint2 q = *(const uint2*)&hfeat[(size_t)sr * HC + f];
            float2 v0 = __half22float2(*(__half2*)&q.x);
            float2 v1 = __half22float2(*(__half2*)&q.y);
            ax += e * v0.x; ay += e * v0.y;
            az += e * v1.x; aw += e * v1.y;
            wsum += e;
        }
        if (j0 + CH < s1) __syncthreads();
    }

    float iv = 1.f / wsum;
    float4 bv = *(const float4*)&bias[f];
    float ox = ax * iv + bv.x;
    float oy = ay * iv + bv.y;
    float oz = az * iv + bv.z;
    float ow = aw * iv + bv.w;
    if (LAYER == 1) {
        ox = ox > 0.f ? ox : 0.f;
        oy = oy > 0.f ? oy : 0.f;
        oz = oz > 0.f ? oz : 0.f;
        ow = ow > 0.f ? ow : 0.f;
        uint2 q;
        *(__half2*)&q.x = __floats2half2_rn(ox, oy);
        *(__half2*)&q.y = __floats2half2_rn(oz, ow);
        *(uint2*)&g_o1h[(size_t)n * HC + f] = q;
    } else {
        *(float4*)&out_param[(size_t)n * HC + f] = make_float4(ox, oy, oz, ow);
    }
}

// ---------------- launch ----------------
extern "C" void kernel_launch(void* const* d_in, const int* in_sizes, int n_in,
                              void* d_out, int out_size)
{
    const float* x   = (const float*)d_in[0];
    const void*  ei  = d_in[1];
    const float* W1  = (const float*)d_in[2];
    const float* as1 = (const float*)d_in[3];
    const float* ad1 = (const float*)d_in[4];
    const float* b1  = (const float*)d_in[5];
    const float* W2  = (const float*)d_in[6];
    const float* as2 = (const float*)d_in[7];
    const float* ad2 = (const float*)d_in[8];
    const float* b2  = (const float*)d_in[9];
    float* out = (float*)d_out;

    static cudaStream_t s_side = nullptr;
    static cudaEvent_t  s_evFork = nullptr, s_evCSR = nullptr;
    if (!s_side) {
        cudaStreamCreateWithFlags(&s_side, cudaStreamNonBlocking);
        cudaEventCreateWithFlags(&s_evFork, cudaEventDisableTiming);
        cudaEventCreateWithFlags(&s_evCSR,  cudaEventDisableTiming);
    }

    // fork immediately: CSR chain (side) ∥ convert + gemm1 (main)
    cudaEventRecord(s_evFork, 0);
    cudaStreamWaitEvent(s_side, s_evFork, 0);

    init_kernel<<<NB, 256, 0, s_side>>>((const int*)ei);
    hist_kernel<<<(NE4 + 255) / 256, 256, 0, s_side>>>(ei);
    scan_kernel<<<NB, 256, 0, s_side>>>();
    scatter_kernel<<<(SCAT_T + 255) / 256, 256, 0, s_side>>>(ei);
    cudaEventRecord(s_evCSR, s_side);

    conv_kernel<<<(N_NODES * 256 / 4 + 255) / 256, 256>>>(x, W1, W2);
    gemm_kernel<1><<<dim3((N_NODES + 127) / 128, 2), 256>>>(N_NODES, 256, as1, ad1);

    // join: aggregate1 needs both gemm1 (main) and CSR (side)
    cudaStreamWaitEvent(0, s_evCSR, 0);

    aggregate_kernel<1, 2, 128><<<N_NODES, 64>>>(b1, nullptr);

    // Layer 2 (sequential dependencies)
    gemm_kernel<2><<<dim3((N_NODES + 127) / 128, 1), 256>>>(N_NODES, 128, as2, ad2);
    aggregate_kernel<2, 1, 128><<<N_NODES, 32>>>(b2, out);
}